// round 17
// baseline (speedup 1.0000x reference)
#include <cuda_runtime.h>
#include <cuda_bf16.h>

#define GRID_N 4
#define WIN    3
#define NWIN   (GRID_N - WIN + 1)   // 2
#define NCELL  (GRID_N * GRID_N)    // 16
#define B_MAX  4096

// ---- Fast path constants (B=128, H=W=512) ----
#define NBATCH  128
#define NUNITS  4096                // 512 stripes * 8 sub-blocks (16 rows each)
#define NCTA_WS 592                 // 148 SMs * 4 CTAs -> 1024 thr/SM everywhere

// Unit partials: [unit][warp(8)]; unique writer per slot.
__device__ float        g_part[NUNITS * 8];
__device__ unsigned int g_cnt[NBATCH];        // 256 warp-arrivals per batch
__device__ unsigned int g_unit_ctr;           // work-stealing counter
__device__ unsigned int g_done;               // CTA exit counter (for reset)
__device__ float        g_cell[B_MAX * NCELL];// generic-fallback scratch

// Persistent work-stealing kernel. Unit u -> (b = u>>5, gy = (u>>3)&3,
// sub = u&7): 16 rows x 512 cols = 2048 float4. Thread t loads k*256 + t,
// k = 0..7 (static, front-batched): column == t&127 -> gx = (t>>5)&3 is
// warp-uniform; warp w covers gx = w&3. Steal atomic is pipelined behind
// the unit's loads. Last warp-arrival per batch runs the fused epilogue.
__global__ __launch_bounds__(256, 4) void ws_kernel(
        const float4* __restrict__ in, float* __restrict__ out) {
    int t    = threadIdx.x;
    int w    = t >> 5;
    int lane = t & 31;

    __shared__ int s_next;
    if (t == 0) s_next = (int)atomicAdd(&g_unit_ctr, 1u);
    __syncthreads();

    for (;;) {
        int u = s_next;                     // uniform across CTA
        if (u >= NUNITS) break;             // uniform exit
        __syncthreads();                    // all read u
        if (t == 0) s_next = (int)atomicAdd(&g_unit_ctr, 1u);  // pipelined

        int b   = u >> 5;
        int gy  = (u >> 3) & 3;
        int sub = u & 7;
        const float4* p = in + (size_t)b * 65536 + gy * 16384 + sub * 2048 + t;

        float4 v0 = __ldcs(p +    0); float4 v1 = __ldcs(p +  256);
        float4 v2 = __ldcs(p +  512); float4 v3 = __ldcs(p +  768);
        float4 v4 = __ldcs(p + 1024); float4 v5 = __ldcs(p + 1280);
        float4 v6 = __ldcs(p + 1536); float4 v7 = __ldcs(p + 1792);
        float a0 = ((v0.x + v0.y) + (v0.z + v0.w)) + ((v1.x + v1.y) + (v1.z + v1.w));
        float a1 = ((v2.x + v2.y) + (v2.z + v2.w)) + ((v3.x + v3.y) + (v3.z + v3.w));
        float a2 = ((v4.x + v4.y) + (v4.z + v4.w)) + ((v5.x + v5.y) + (v5.z + v5.w));
        float a3 = ((v6.x + v6.y) + (v6.z + v6.w)) + ((v7.x + v7.y) + (v7.z + v7.w));
        float acc = (a0 + a1) + (a2 + a3);

#pragma unroll
        for (int o = 16; o > 0; o >>= 1)
            acc += __shfl_down_sync(0xffffffffu, acc, o);

        if (lane == 0) {
            g_part[u * 8 + w] = acc;        // unique slot, no races
            __threadfence();                // release
            unsigned old = atomicAdd(&g_cnt[b], 1u);
            if (old == 255u) {              // last of 32 units * 8 warps
                __threadfence();            // acquire
                float c[NCELL];
#pragma unroll
                for (int gy2 = 0; gy2 < 4; gy2++)
#pragma unroll
                    for (int gx = 0; gx < 4; gx++) {
                        float s = 0.0f;
#pragma unroll
                        for (int sb = 0; sb < 8; sb++) {
                            int u2 = b * 32 + gy2 * 8 + sb;
                            s += __ldcg(&g_part[u2 * 8 + gx])
                               + __ldcg(&g_part[u2 * 8 + gx + 4]);
                        }
                        c[gy2 * 4 + gx] = s;
                    }
                float win[NWIN * NWIN];
#pragma unroll
                for (int r = 0; r < NWIN; r++)
#pragma unroll
                    for (int q = 0; q < NWIN; q++) {
                        float s = 0.0f;
#pragma unroll
                        for (int dr = 0; dr < WIN; dr++)
#pragma unroll
                            for (int dc = 0; dc < WIN; dc++)
                                s += c[(r + dr) * GRID_N + (q + dc)];
                        win[r * NWIN + q] = s;
                    }
                float best = win[0];
                int bi = 0;
#pragma unroll
                for (int k = 1; k < NWIN * NWIN; k++)
                    if (win[k] > best) { best = win[k]; bi = k; }

                out[b * 2 + 0] = (float)(bi >> 1);   // row (float32 output)
                out[b * 2 + 1] = (float)(bi & 1);    // col
                g_cnt[b] = 0u;                       // replay-safe reset
            }
        }
        __syncthreads();                    // s_next update & part visible
    }

    // Reset steal counter for next graph replay (last CTA out).
    if (t == 0) {
        __threadfence();
        unsigned old = atomicAdd(&g_done, 1u);
        if (old == NCTA_WS - 1u) {
            g_unit_ctr = 0u;
            g_done     = 0u;
        }
    }
}

// ---------------- Generic fallback (any square H=W, H%4==0) ----------------
__global__ __launch_bounds__(256) void cell_sum_kernel(
        const float* __restrict__ in, int HW, int W, int gh, int gw) {
    int blk  = blockIdx.x;
    int cell = blk & (NCELL - 1);
    int b    = blk >> 4;
    int gx = cell & (GRID_N - 1);
    int gy = cell >> 2;
    const float* base = in + (size_t)b * HW + (size_t)(gy * gh) * W + (size_t)gx * gw;
    int t = threadIdx.x;
    int n = gh * gw;
    float acc = 0.0f;
    for (int i = t; i < n; i += 256) {
        int r = i / gw;
        int c = i - r * gw;
        acc += base[(size_t)r * W + c];
    }
    __shared__ float sh[256];
    sh[t] = acc;
    __syncthreads();
#pragma unroll
    for (int s = 128; s > 0; s >>= 1) {
        if (t < s) sh[t] += sh[t + s];
        __syncthreads();
    }
    if (t == 0) g_cell[blk] = sh[0];
}

__global__ void select_kernel(float* __restrict__ out, int B) {
    int b = blockIdx.x * blockDim.x + threadIdx.x;
    if (b >= B) return;
    float c[NCELL];
#pragma unroll
    for (int i = 0; i < NCELL; i++) c[i] = g_cell[b * NCELL + i];
    float win[NWIN * NWIN];
#pragma unroll
    for (int r = 0; r < NWIN; r++)
#pragma unroll
        for (int q = 0; q < NWIN; q++) {
            float s = 0.0f;
#pragma unroll
            for (int dr = 0; dr < WIN; dr++)
#pragma unroll
                for (int dc = 0; dc < WIN; dc++)
                    s += c[(r + dr) * GRID_N + (q + dc)];
            win[r * NWIN + q] = s;
        }
    float best = win[0];
    int bi = 0;
#pragma unroll
    for (int k = 1; k < NWIN * NWIN; k++)
        if (win[k] > best) { best = win[k]; bi = k; }
    out[b * 2 + 0] = (float)(bi / NWIN);
    out[b * 2 + 1] = (float)(bi % NWIN);
}

extern "C" void kernel_launch(void* const* d_in, const int* in_sizes, int n_in,
                              void* d_out, int out_size) {
    int best_i = 0;
    for (int i = 1; i < n_in; i++)
        if (in_sizes[i] > in_sizes[best_i]) best_i = i;
    const float* in = (const float*)d_in[best_i];
    float* out = (float*)d_out;

    int B = out_size / 2;
    if (B < 1) B = 1;
    long long HW = (long long)in_sizes[best_i] / B;

    if (B == NBATCH && HW == 512LL * 512LL) {
        ws_kernel<<<NCTA_WS, 256>>>((const float4*)in, out);
    } else {
        if (B > B_MAX) B = B_MAX;
        int H = 1;
        while ((long long)(H + 1) * (H + 1) <= HW) H++;
        int W = H;
        cell_sum_kernel<<<B * NCELL, 256>>>(in, (int)HW, W, H / GRID_N, W / GRID_N);
        select_kernel<<<(B + 127) / 128, 128>>>(out, B);
    }
}